// round 1
// baseline (speedup 1.0000x reference)
#include <cuda_runtime.h>
#include <math.h>

// ---------------------------------------------------------------------------
// EncoderBlock: pre-norm transformer block, fp32 baseline.
//   x:[2,2048,1024]  H=16 Dk=64  Dff=4096
// Pipeline: LN1 -> QKV GEMMs -> scores(NT,batched) -> softmax -> ctx(NN,batched)
//           -> Wo GEMM(+resid) -> LN2 -> FFN1(+b1,relu) -> FFN2(+b2,+resid)
// ---------------------------------------------------------------------------

#define DMODEL 1024
#define NHEADS 16
#define DK 64
#define DFF 4096
#define BATCH 2
#define SEQ 2048
#define NTOK (BATCH * SEQ)           // 4096
#define LN_EPS 1e-5f

// Scratch (device-global; no allocations allowed)
__device__ float g_xn [(size_t)NTOK * DMODEL];
__device__ float g_q  [(size_t)NTOK * DMODEL];
__device__ float g_k  [(size_t)NTOK * DMODEL];
__device__ float g_v  [(size_t)NTOK * DMODEL];
__device__ float g_ctx[(size_t)NTOK * DMODEL];
__device__ float g_x1 [(size_t)NTOK * DMODEL];
__device__ float g_ffh[(size_t)NTOK * DFF];
__device__ float g_scores[(size_t)BATCH * NHEADS * SEQ * SEQ];   // 512 MB

// ---------------------------------------------------------------------------
// Reductions
// ---------------------------------------------------------------------------
__device__ __forceinline__ float warpReduceSum(float v) {
    #pragma unroll
    for (int o = 16; o > 0; o >>= 1) v += __shfl_down_sync(0xffffffffu, v, o);
    return v;
}
__device__ __forceinline__ float warpReduceMax(float v) {
    #pragma unroll
    for (int o = 16; o > 0; o >>= 1) v = fmaxf(v, __shfl_down_sync(0xffffffffu, v, o));
    return v;
}
// 256-thread block reduce; reentrant-safe (trailing barrier).
__device__ __forceinline__ float blockReduceSum(float v) {
    __shared__ float sh[8];
    int lane = threadIdx.x & 31, w = threadIdx.x >> 5;
    v = warpReduceSum(v);
    if (lane == 0) sh[w] = v;
    __syncthreads();
    if (w == 0) {
        float t = (lane < 8) ? sh[lane] : 0.0f;
        t = warpReduceSum(t);
        if (lane == 0) sh[0] = t;
    }
    __syncthreads();
    float r = sh[0];
    __syncthreads();
    return r;
}
__device__ __forceinline__ float blockReduceMax(float v) {
    __shared__ float sh[8];
    int lane = threadIdx.x & 31, w = threadIdx.x >> 5;
    v = warpReduceMax(v);
    if (lane == 0) sh[w] = v;
    __syncthreads();
    if (w == 0) {
        float t = (lane < 8) ? sh[lane] : -INFINITY;
        t = warpReduceMax(t);
        if (lane == 0) sh[0] = t;
    }
    __syncthreads();
    float r = sh[0];
    __syncthreads();
    return r;
}

// ---------------------------------------------------------------------------
// LayerNorm (faithful: unbiased std ddof=1, eps added to std)
// one block (256 thr) per row of 1024
// ---------------------------------------------------------------------------
__global__ void __launch_bounds__(256) ln_kernel(
    const float* __restrict__ x, float* __restrict__ out,
    const float* __restrict__ alpha_p, const float* __restrict__ bias_p)
{
    int row = blockIdx.x;
    const float* xr = x + (size_t)row * DMODEL;
    float* orow = out + (size_t)row * DMODEL;
    int t = threadIdx.x;
    float v[4];
    float s = 0.f, sq = 0.f;
    #pragma unroll
    for (int i = 0; i < 4; i++) {
        v[i] = xr[t + 256 * i];
        s += v[i];
        sq += v[i] * v[i];
    }
    s  = blockReduceSum(s);
    sq = blockReduceSum(sq);
    float mean = s * (1.0f / DMODEL);
    float var  = (sq - (float)DMODEL * mean * mean) * (1.0f / (DMODEL - 1));
    var = fmaxf(var, 0.0f);
    float scale = alpha_p[0] / (sqrtf(var) + LN_EPS);
    float bias  = bias_p[0];
    #pragma unroll
    for (int i = 0; i < 4; i++)
        orow[t + 256 * i] = (v[i] - mean) * scale + bias;
}

// ---------------------------------------------------------------------------
// Generic NN GEMM: C[M,N] = act(A[M,K] @ B[K,N] + bias? + resid?)
// 64x64 tile, BK=16, 256 threads, 4x4 per thread.
// All dims assumed divisible (M=4096, N in {1024,4096}, K in {1024,4096}).
// ---------------------------------------------------------------------------
template <bool RELU>
__global__ void __launch_bounds__(256) gemm_nn(
    const float* __restrict__ A, const float* __restrict__ Bm,
    float* __restrict__ C, int M, int N, int K,
    const float* __restrict__ bias, const float* __restrict__ resid)
{
    __shared__ float As[64][17];   // padded: conflict-free column reads
    __shared__ float Bs[16][64];
    int bn = blockIdx.x * 64, bm = blockIdx.y * 64;
    int tid = threadIdx.x;
    int tr4 = (tid >> 4) * 4, tc4 = (tid & 15) * 4;
    int arow = tid >> 2,  ac4 = (tid & 3) * 4;
    int brow = tid >> 4,  bc4 = (tid & 15) * 4;

    float acc[4][4] = {};

    for (int k0 = 0; k0 < K; k0 += 16) {
        float4 av = *(const float4*)(A + (size_t)(bm + arow) * K + k0 + ac4);
        As[arow][ac4 + 0] = av.x; As[arow][ac4 + 1] = av.y;
        As[arow][ac4 + 2] = av.z; As[arow][ac4 + 3] = av.w;
        float4 bv = *(const float4*)(Bm + (size_t)(k0 + brow) * N + bn + bc4);
        *(float4*)&Bs[brow][bc4] = bv;
        __syncthreads();
        #pragma unroll
        for (int kk = 0; kk < 16; kk++) {
            float a0 = As[tr4 + 0][kk];
            float a1 = As[tr4 + 1][kk];
            float a2 = As[tr4 + 2][kk];
            float a3 = As[tr4 + 3][kk];
            float4 b = *(const float4*)&Bs[kk][tc4];
            acc[0][0] = fmaf(a0, b.x, acc[0][0]); acc[0][1] = fmaf(a0, b.y, acc[0][1]);
            acc[0][2] = fmaf(a0, b.z, acc[0][2]); acc[0][3] = fmaf(a0, b.w, acc[0][3]);
            acc[1][0] = fmaf(a1, b.x, acc[1][0]); acc[1][1] = fmaf(a1, b.y, acc[1][1]);
            acc[1][2] = fmaf(a1, b.z, acc[1][2]); acc[1][3] = fmaf(a1, b.w, acc[1][3]);
            acc[2][0] = fmaf(a2, b.x, acc[2][0]); acc[2][1] = fmaf(a2, b.y, acc[2][1]);
            acc[2][2] = fmaf(a2, b.z, acc[2][2]); acc[2][3] = fmaf(a2, b.w, acc[2][3]);
            acc[3][0] = fmaf(a3, b.x, acc[3][0]); acc[3][1] = fmaf(a3, b.y, acc[3][1]);
            acc[3][2] = fmaf(a3, b.z, acc[3][2]); acc[3][3] = fmaf(a3, b.w, acc[3][3]);
        }
        __syncthreads();
    }

    #pragma unroll
    for (int i = 0; i < 4; i++) {
        int r = bm + tr4 + i;
        float* crow = C + (size_t)r * N + bn + tc4;
        #pragma unroll
        for (int j = 0; j < 4; j++) {
            float vv = acc[i][j];
            if (bias)  vv += bias[bn + tc4 + j];
            if (resid) vv += resid[(size_t)r * N + bn + tc4 + j];
            if (RELU)  vv = fmaxf(vv, 0.0f);
            crow[j] = vv;
        }
    }
}

// ---------------------------------------------------------------------------
// Attention scores: scores[b,h,m,n] = (q_bh[m,:] . k_bh[n,:]) / 8, mask applied.
// q,k layout: [B,S,H*Dk]; 64x64 output tile per block; full K=64 in smem.
// ---------------------------------------------------------------------------
__global__ void __launch_bounds__(256) attn_scores(
    const float* __restrict__ q, const float* __restrict__ k,
    const int* __restrict__ mask, float* __restrict__ scores)
{
    __shared__ float Qs[64][DK + 1];
    __shared__ float Ks[64][DK + 1];
    int z = blockIdx.z, b = z >> 4, h = z & 15;
    int n0 = blockIdx.x * 64, m0 = blockIdx.y * 64;
    const float* qb = q + (size_t)b * SEQ * DMODEL + h * DK;
    const float* kb = k + (size_t)b * SEQ * DMODEL + h * DK;
    float* sc = scores + (size_t)z * SEQ * SEQ;
    int tid = threadIdx.x;

    int lr = tid >> 2;             // 0..63
    int lc = (tid & 3) * 16;       // 0,16,32,48
    #pragma unroll
    for (int j = 0; j < 4; j++) {
        float4 qv = *(const float4*)(qb + (size_t)(m0 + lr) * DMODEL + lc + j * 4);
        Qs[lr][lc + j * 4 + 0] = qv.x; Qs[lr][lc + j * 4 + 1] = qv.y;
        Qs[lr][lc + j * 4 + 2] = qv.z; Qs[lr][lc + j * 4 + 3] = qv.w;
        float4 kv = *(const float4*)(kb + (size_t)(n0 + lr) * DMODEL + lc + j * 4);
        Ks[lr][lc + j * 4 + 0] = kv.x; Ks[lr][lc + j * 4 + 1] = kv.y;
        Ks[lr][lc + j * 4 + 2] = kv.z; Ks[lr][lc + j * 4 + 3] = kv.w;
    }
    __syncthreads();

    int tr4 = (tid >> 4) * 4, tc4 = (tid & 15) * 4;
    float acc[4][4] = {};
    #pragma unroll 8
    for (int kk = 0; kk < DK; kk++) {
        float a0 = Qs[tr4 + 0][kk], a1 = Qs[tr4 + 1][kk];
        float a2 = Qs[tr4 + 2][kk], a3 = Qs[tr4 + 3][kk];
        float b0 = Ks[tc4 + 0][kk], b1 = Ks[tc4 + 1][kk];
        float b2 = Ks[tc4 + 2][kk], b3 = Ks[tc4 + 3][kk];
        acc[0][0] = fmaf(a0, b0, acc[0][0]); acc[0][1] = fmaf(a0, b1, acc[0][1]);
        acc[0][2] = fmaf(a0, b2, acc[0][2]); acc[0][3] = fmaf(a0, b3, acc[0][3]);
        acc[1][0] = fmaf(a1, b0, acc[1][0]); acc[1][1] = fmaf(a1, b1, acc[1][1]);
        acc[1][2] = fmaf(a1, b2, acc[1][2]); acc[1][3] = fmaf(a1, b3, acc[1][3]);
        acc[2][0] = fmaf(a2, b0, acc[2][0]); acc[2][1] = fmaf(a2, b1, acc[2][1]);
        acc[2][2] = fmaf(a2, b2, acc[2][2]); acc[2][3] = fmaf(a2, b3, acc[2][3]);
        acc[3][0] = fmaf(a3, b0, acc[3][0]); acc[3][1] = fmaf(a3, b1, acc[3][1]);
        acc[3][2] = fmaf(a3, b2, acc[3][2]); acc[3][3] = fmaf(a3, b3, acc[3][3]);
    }

    const int* mrow = mask + b * SEQ;
    #pragma unroll
    for (int i = 0; i < 4; i++) {
        #pragma unroll
        for (int j = 0; j < 4; j++) {
            float vv = acc[i][j] * 0.125f;     // 1/sqrt(64)
            if (mrow[n0 + tc4 + j] == 0) vv = -1e9f;
            sc[(size_t)(m0 + tr4 + i) * SEQ + n0 + tc4 + j] = vv;
        }
    }
}

// ---------------------------------------------------------------------------
// Row softmax over last dim (2048). One 256-thread block per row; 8 elems/thr.
// ---------------------------------------------------------------------------
__global__ void __launch_bounds__(256) softmax_kernel(float* __restrict__ scores) {
    size_t row = blockIdx.x;
    float* r = scores + row * (size_t)SEQ;
    int t = threadIdx.x;
    float v[8];
    float m = -INFINITY;
    #pragma unroll
    for (int i = 0; i < 8; i++) { v[i] = r[t + 256 * i]; m = fmaxf(m, v[i]); }
    m = blockReduceMax(m);
    float s = 0.f;
    #pragma unroll
    for (int i = 0; i < 8; i++) { v[i] = __expf(v[i] - m); s += v[i]; }
    s = blockReduceSum(s);
    float inv = 1.0f / s;
    #pragma unroll
    for (int i = 0; i < 8; i++) r[t + 256 * i] = v[i] * inv;
}

// ---------------------------------------------------------------------------
// ctx[b,m,h*64+n] = sum_k attn[b,h,m,k] * v[b,k,h*64+n]
// Batched 64x64(xN=64) GEMM, BK=16.
// ---------------------------------------------------------------------------
__global__ void __launch_bounds__(256) attn_ctx(
    const float* __restrict__ scores, const float* __restrict__ v,
    float* __restrict__ ctx)
{
    __shared__ float As[64][17];
    __shared__ float Bs[16][DK];
    int z = blockIdx.z, b = z >> 4, h = z & 15;
    const float* A  = scores + (size_t)z * SEQ * SEQ;
    const float* Vb = v + (size_t)b * SEQ * DMODEL + h * DK;
    float* C        = ctx + (size_t)b * SEQ * DMODEL + h * DK;
    int m0 = blockIdx.y * 64;
    int tid = threadIdx.x;
    int tr4 = (tid >> 4) * 4, tc4 = (tid & 15) * 4;
    int arow = tid >> 2, ac4 = (tid & 3) * 4;
    int brow = tid >> 4, bc4 = (tid & 15) * 4;

    float acc[4][4] = {};
    for (int k0 = 0; k0 < SEQ; k0 += 16) {
        float4 av = *(const float4*)(A + (size_t)(m0 + arow) * SEQ + k0 + ac4);
        As[arow][ac4 + 0] = av.x; As[arow][ac4 + 1] = av.y;
        As[arow][ac4 + 2] = av.z; As[arow][ac4 + 3] = av.w;
        float4 bv = *(const float4*)(Vb + (size_t)(k0 + brow) * DMODEL + bc4);
        *(float4*)&Bs[brow][bc4] = bv;
        __syncthreads();
        #pragma unroll
        for (int kk = 0; kk < 16; kk++) {
            float a0 = As[tr4 + 0][kk];
            float a1 = As[tr4 + 1][kk];
            float a2 = As[tr4 + 2][kk];
            float a3 = As[tr4 + 3][kk];
            float4 bq = *(const float4*)&Bs[kk][tc4];
            acc[0][0] = fmaf(a0, bq.x, acc[0][0]); acc[0][1] = fmaf(a0, bq.y, acc[0][1]);
            acc[0][2] = fmaf(a0, bq.z, acc[0][2]); acc[0][3] = fmaf(a0, bq.w, acc[0][3]);
            acc[1][0] = fmaf(a1, bq.x, acc[1][0]); acc[1][1] = fmaf(a1, bq.y, acc[1][1]);
            acc[1][2] = fmaf(a1, bq.z, acc[1][2]); acc[1][3] = fmaf(a1, bq.w, acc[1][3]);
            acc[2][0] = fmaf(a2, bq.x, acc[2][0]); acc[2][1] = fmaf(a2, bq.y, acc[2][1]);
            acc[2][2] = fmaf(a2, bq.z, acc[2][2]); acc[2][3] = fmaf(a2, bq.w, acc[2][3]);
            acc[3][0] = fmaf(a3, bq.x, acc[3][0]); acc[3][1] = fmaf(a3, bq.y, acc[3][1]);
            acc[3][2] = fmaf(a3, bq.z, acc[3][2]); acc[3][3] = fmaf(a3, bq.w, acc[3][3]);
        }
        __syncthreads();
    }

    #pragma unroll
    for (int i = 0; i < 4; i++) {
        float* crow = C + (size_t)(m0 + tr4 + i) * DMODEL + tc4;
        #pragma unroll
        for (int j = 0; j < 4; j++) crow[j] = acc[i][j];
    }
}

// ---------------------------------------------------------------------------
// Launch
// ---------------------------------------------------------------------------
extern "C" void kernel_launch(void* const* d_in, const int* in_sizes, int n_in,
                              void* d_out, int out_size)
{
    const float* x      = (const float*)d_in[0];
    const int*   mask   = (const int*)  d_in[1];
    const float* wq     = (const float*)d_in[2];
    const float* wk     = (const float*)d_in[3];
    const float* wv     = (const float*)d_in[4];
    const float* wo     = (const float*)d_in[5];
    const float* w1     = (const float*)d_in[6];
    const float* b1     = (const float*)d_in[7];
    const float* w2     = (const float*)d_in[8];
    const float* b2     = (const float*)d_in[9];
    const float* alpha1 = (const float*)d_in[10];
    const float* bias1  = (const float*)d_in[11];
    const float* alpha2 = (const float*)d_in[12];
    const float* bias2  = (const float*)d_in[13];
    float* out = (float*)d_out;

    float *xn, *q, *k, *v, *ctx, *x1, *ffh, *scores;
    cudaGetSymbolAddress((void**)&xn,     g_xn);
    cudaGetSymbolAddress((void**)&q,      g_q);
    cudaGetSymbolAddress((void**)&k,      g_k);
    cudaGetSymbolAddress((void**)&v,      g_v);
    cudaGetSymbolAddress((void**)&ctx,    g_ctx);
    cudaGetSymbolAddress((void**)&x1,     g_x1);
    cudaGetSymbolAddress((void**)&ffh,    g_ffh);
    cudaGetSymbolAddress((void**)&scores, g_scores);

    // Sublayer 1
    ln_kernel<<<NTOK, 256>>>(x, xn, alpha1, bias1);

    dim3 gQKV(DMODEL / 64, NTOK / 64);              // (16, 64)
    gemm_nn<false><<<gQKV, 256>>>(xn, wq, q, NTOK, DMODEL, DMODEL, nullptr, nullptr);
    gemm_nn<false><<<gQKV, 256>>>(xn, wk, k, NTOK, DMODEL, DMODEL, nullptr, nullptr);
    gemm_nn<false><<<gQKV, 256>>>(xn, wv, v, NTOK, DMODEL, DMODEL, nullptr, nullptr);

    dim3 gSc(SEQ / 64, SEQ / 64, BATCH * NHEADS);   // (32, 32, 32)
    attn_scores<<<gSc, 256>>>(q, k, mask, scores);

    softmax_kernel<<<BATCH * NHEADS * SEQ, 256>>>(scores);

    dim3 gCtx(1, SEQ / 64, BATCH * NHEADS);         // (1, 32, 32)
    attn_ctx<<<gCtx, 256>>>(scores, v, ctx);

    // Wo projection + residual (x)
    gemm_nn<false><<<gQKV, 256>>>(ctx, wo, x1, NTOK, DMODEL, DMODEL, nullptr, x);

    // Sublayer 2
    ln_kernel<<<NTOK, 256>>>(x1, xn, alpha2, bias2);

    dim3 gF1(DFF / 64, NTOK / 64);                  // (64, 64)
    gemm_nn<true><<<gF1, 256>>>(xn, w1, ffh, NTOK, DFF, DMODEL, b1, nullptr);

    dim3 gF2(DMODEL / 64, NTOK / 64);               // (16, 64)
    gemm_nn<false><<<gF2, 256>>>(ffh, w2, out, NTOK, DMODEL, DFF, b2, x1);
}

// round 2
// speedup vs baseline: 1.4216x; 1.4216x over previous
#include <cuda_runtime.h>
#include <math.h>

#define DMODEL 1024
#define NHEADS 16
#define DK 64
#define DFF 4096
#define BATCH 2
#define SEQ 2048
#define NTOK (BATCH * SEQ)           // 4096
#define LN_EPS 1e-5f

typedef unsigned long long ull;

// ---------------------------------------------------------------------------
// Scratch (device-global; no allocations allowed)
// ---------------------------------------------------------------------------
__device__ float g_xn [(size_t)NTOK * DMODEL];
__device__ float g_q  [(size_t)NTOK * DMODEL];
__device__ float g_k  [(size_t)NTOK * DMODEL];
__device__ float g_v  [(size_t)NTOK * DMODEL];
__device__ float g_ctx[(size_t)NTOK * DMODEL];
__device__ float g_x1 [(size_t)NTOK * DMODEL];
__device__ float g_ffh[(size_t)NTOK * DFF];
__device__ float g_scores[(size_t)BATCH * NHEADS * SEQ * SEQ];   // 512 MB

// ---------------------------------------------------------------------------
// Packed fp32x2 helpers (SASS FFMA2 — 2x fp32 FMA throughput, PTX-only path)
// ---------------------------------------------------------------------------
__device__ __forceinline__ ull pk2(float x) {
    ull r; asm("mov.b64 %0, {%1,%1};" : "=l"(r) : "f"(x)); return r;
}
__device__ __forceinline__ void fma2(ull& d, ull a, ull b) {
    asm("fma.rn.f32x2 %0, %1, %2, %0;" : "+l"(d) : "l"(a), "l"(b));
}
__device__ __forceinline__ float2 unpk(ull v) {
    float2 r; asm("mov.b64 {%0,%1}, %2;" : "=f"(r.x), "=f"(r.y) : "l"(v)); return r;
}

// ---------------------------------------------------------------------------
// Reductions
// ---------------------------------------------------------------------------
__device__ __forceinline__ float warpReduceSum(float v) {
    #pragma unroll
    for (int o = 16; o > 0; o >>= 1) v += __shfl_down_sync(0xffffffffu, v, o);
    return v;
}
__device__ __forceinline__ float warpReduceMax(float v) {
    #pragma unroll
    for (int o = 16; o > 0; o >>= 1) v = fmaxf(v, __shfl_down_sync(0xffffffffu, v, o));
    return v;
}
__device__ __forceinline__ float blockReduceSum(float v) {
    __shared__ float sh[8];
    int lane = threadIdx.x & 31, w = threadIdx.x >> 5;
    v = warpReduceSum(v);
    if (lane == 0) sh[w] = v;
    __syncthreads();
    if (w == 0) {
        float t = (lane < 8) ? sh[lane] : 0.0f;
        t = warpReduceSum(t);
        if (lane == 0) sh[0] = t;
    }
    __syncthreads();
    float r = sh[0];
    __syncthreads();
    return r;
}
__device__ __forceinline__ float blockReduceMax(float v) {
    __shared__ float sh[8];
    int lane = threadIdx.x & 31, w = threadIdx.x >> 5;
    v = warpReduceMax(v);
    if (lane == 0) sh[w] = v;
    __syncthreads();
    if (w == 0) {
        float t = (lane < 8) ? sh[lane] : -INFINITY;
        t = warpReduceMax(t);
        if (lane == 0) sh[0] = t;
    }
    __syncthreads();
    float r = sh[0];
    __syncthreads();
    return r;
}

// ---------------------------------------------------------------------------
// LayerNorm (faithful: unbiased std ddof=1, eps added to std)
// ---------------------------------------------------------------------------
__global__ void __launch_bounds__(256) ln_kernel(
    const float* __restrict__ x, float* __restrict__ out,
    const float* __restrict__ alpha_p, const float* __restrict__ bias_p)
{
    int row = blockIdx.x;
    const float* xr = x + (size_t)row * DMODEL;
    float* orow = out + (size_t)row * DMODEL;
    int t = threadIdx.x;
    float v[4];
    float s = 0.f, sq = 0.f;
    #pragma unroll
    for (int i = 0; i < 4; i++) {
        v[i] = xr[t + 256 * i];
        s += v[i];
        sq += v[i] * v[i];
    }
    s  = blockReduceSum(s);
    sq = blockReduceSum(sq);
    float mean = s * (1.0f / DMODEL);
    float var  = (sq - (float)DMODEL * mean * mean) * (1.0f / (DMODEL - 1));
    var = fmaxf(var, 0.0f);
    float scale = alpha_p[0] / (sqrtf(var) + LN_EPS);
    float bias  = bias_p[0];
    #pragma unroll
    for (int i = 0; i < 4; i++)
        orow[t + 256 * i] = (v[i] - mean) * scale + bias;
}

// ---------------------------------------------------------------------------
// Row softmax over last dim (2048). One 256-thread block per row.
// ---------------------------------------------------------------------------
__global__ void __launch_bounds__(256) softmax_kernel(float* __restrict__ scores) {
    size_t row = blockIdx.x;
    float* r = scores + row * (size_t)SEQ;
    int t = threadIdx.x;
    float v[8];
    float m = -INFINITY;
    #pragma unroll
    for (int i = 0; i < 8; i++) { v[i] = r[t + 256 * i]; m = fmaxf(m, v[i]); }
    m = blockReduceMax(m);
    float s = 0.f;
    #pragma unroll
    for (int i = 0; i < 8; i++) { v[i] = __expf(v[i] - m); s += v[i]; }
    s = blockReduceSum(s);
    float inv = 1.0f / s;
    #pragma unroll
    for (int i = 0; i < 8; i++) r[t + 256 * i] = v[i] * inv;
}

// ---------------------------------------------------------------------------
// GEMM core: 128(M) x TN(N) tile, BK=8, 256 threads, double-buffered smem.
// Each thread: 8 rows (as 4 f32x2 row-pairs) x NC cols via fma.rn.f32x2.
// BT: B is [N,K] row-major (NT gemm, used for attention scores).
// EPI: 0 plain | 1 bias+relu | 2 bias+resid | 3 resid | 4 scale+mask (scores)
// All dims assumed divisible by tile sizes (true for this problem).
// ---------------------------------------------------------------------------
template<int TN, bool BT, int EPI>
__device__ __forceinline__ void gemm_core(
    const float* __restrict__ A, const float* __restrict__ B, float* __restrict__ C,
    int K, int lda, int ldb, int ldc,
    const float* __restrict__ bias, const float* __restrict__ resid,
    const int* __restrict__ mask, int bm, int bn)
{
    constexpr int BSTR = BT ? 132 : TN;
    constexpr int NC   = (TN == 128) ? 8 : 4;
    __shared__ float As[2 * 8 * 132];
    __shared__ float Bs[2 * 8 * BSTR];
    const int tid = threadIdx.x;

    // A tile loads: 128 rows x 8 k, one float4 per thread
    const int arow = tid >> 1, ac = (tid & 1) * 4;
    const float* Ap = A + (size_t)(bm + arow) * lda + ac;

    // B tile loads
    int brow, bc;
    const float* Bp;
    if (BT)           { brow = tid >> 1; bc = (tid & 1) * 4;
                        Bp = B + (size_t)(bn + brow) * ldb + bc; }
    else if (TN==128) { brow = tid >> 5; bc = (tid & 31) * 4;
                        Bp = B + (size_t)brow * ldb + bn + bc; }
    else              { brow = tid >> 5; bc = (tid & 31) * 2;
                        Bp = B + (size_t)brow * ldb + bn + bc; }

    const int tx = tid & 15, ty = tid >> 4;
    const int r0 = ty * 4, r1 = 64 + ty * 4;
    const int c0 = tx * 4, c1 = 64 + tx * 4;

    ull acc[4][NC];
    #pragma unroll
    for (int i = 0; i < 4; i++)
        #pragma unroll
        for (int j = 0; j < NC; j++) acc[i][j] = 0ull;

    float4 aR = *(const float4*)Ap;
    float4 bR4;
    float2 bR2;
    if (BT || TN == 128) bR4 = *(const float4*)Bp;
    else                 bR2 = *(const float2*)Bp;

    // store tile 0
    {
        float* sa = As;
        sa[(ac+0)*132 + arow] = aR.x; sa[(ac+1)*132 + arow] = aR.y;
        sa[(ac+2)*132 + arow] = aR.z; sa[(ac+3)*132 + arow] = aR.w;
        float* sb = Bs;
        if (BT) {
            sb[(bc+0)*132 + brow] = bR4.x; sb[(bc+1)*132 + brow] = bR4.y;
            sb[(bc+2)*132 + brow] = bR4.z; sb[(bc+3)*132 + brow] = bR4.w;
        } else if (TN == 128) {
            *(float4*)&sb[brow*BSTR + bc] = bR4;
        } else {
            *(float2*)&sb[brow*BSTR + bc] = bR2;
        }
    }
    __syncthreads();

    const int nt = K >> 3;
    int p = 0;
    for (int kt = 0; kt < nt; kt++) {
        const bool has = (kt + 1 < nt);
        if (has) {
            Ap += 8; aR = *(const float4*)Ap;
            if (BT) { Bp += 8; bR4 = *(const float4*)Bp; }
            else    { Bp += (size_t)8 * ldb;
                      if (TN == 128) bR4 = *(const float4*)Bp;
                      else           bR2 = *(const float2*)Bp; }
        }
        const float* sa = As + p * (8 * 132);
        const float* sb = Bs + p * (8 * BSTR);
        #pragma unroll
        for (int kk = 0; kk < 8; kk++) {
            ull a0 = *(const ull*)(sa + kk*132 + r0);
            ull a1 = *(const ull*)(sa + kk*132 + r0 + 2);
            ull a2 = *(const ull*)(sa + kk*132 + r1);
            ull a3 = *(const ull*)(sa + kk*132 + r1 + 2);
            {
                float4 bl = *(const float4*)(sb + kk*BSTR + c0);
                ull b0 = pk2(bl.x), b1 = pk2(bl.y), b2 = pk2(bl.z), b3 = pk2(bl.w);
                fma2(acc[0][0],a0,b0); fma2(acc[1][0],a1,b0); fma2(acc[2][0],a2,b0); fma2(acc[3][0],a3,b0);
                fma2(acc[0][1],a0,b1); fma2(acc[1][1],a1,b1); fma2(acc[2][1],a2,b1); fma2(acc[3][1],a3,b1);
                fma2(acc[0][2],a0,b2); fma2(acc[1][2],a1,b2); fma2(acc[2][2],a2,b2); fma2(acc[3][2],a3,b2);
                fma2(acc[0][3],a0,b3); fma2(acc[1][3],a1,b3); fma2(acc[2][3],a2,b3); fma2(acc[3][3],a3,b3);
            }
            if (TN == 128) {
                float4 bh = *(const float4*)(sb + kk*BSTR + c1);
                ull b4 = pk2(bh.x), b5 = pk2(bh.y), b6 = pk2(bh.z), b7 = pk2(bh.w);
                fma2(acc[0][4],a0,b4); fma2(acc[1][4],a1,b4); fma2(acc[2][4],a2,b4); fma2(acc[3][4],a3,b4);
                fma2(acc[0][5],a0,b5); fma2(acc[1][5],a1,b5); fma2(acc[2][5],a2,b5); fma2(acc[3][5],a3,b5);
                fma2(acc[0][6],a0,b6); fma2(acc[1][6],a1,b6); fma2(acc[2][6],a2,b6); fma2(acc[3][6],a3,b6);
                fma2(acc[0][7],a0,b7); fma2(acc[1][7],a1,b7); fma2(acc[2][7],a2,b7); fma2(acc[3][7],a3,b7);
            }
        }
        if (has) {
            float* sa2 = As + (p^1) * (8 * 132);
            sa2[(ac+0)*132 + arow] = aR.x; sa2[(ac+1)*132 + arow] = aR.y;
            sa2[(ac+2)*132 + arow] = aR.z; sa2[(ac+3)*132 + arow] = aR.w;
            float* sb2 = Bs + (p^1) * (8 * BSTR);
            if (BT) {
                sb2[(bc+0)*132 + brow] = bR4.x; sb2[(bc+1)*132 + brow] = bR4.y;
                sb2[(bc+2)*132 + brow] = bR4.z; sb2[(bc+3)*132 + brow] = bR4.w;
            } else if (TN == 128) {
                *(float4*)&sb2[brow*BSTR + bc] = bR4;
            } else {
                *(float2*)&sb2[brow*BSTR + bc] = bR2;
            }
        }
        __syncthreads();
        p ^= 1;
    }

    // Epilogue
    #pragma unroll
    for (int rp = 0; rp < 4; rp++) {
        const int rloc = (rp < 2) ? (r0 + rp * 2) : (r1 + (rp - 2) * 2);
        float lo[NC], hi[NC];
        #pragma unroll
        for (int j = 0; j < NC; j++) { float2 t = unpk(acc[rp][j]); lo[j] = t.x; hi[j] = t.y; }
        #pragma unroll
        for (int h = 0; h < 2; h++) {
            const int r = bm + rloc + h;
            float* Crow = C + (size_t)r * ldc;
            #pragma unroll
            for (int g = 0; g < (TN == 128 ? 2 : 1); g++) {
                const int cbase = (g == 0) ? c0 : c1;
                float v0 = (h ? hi[g*4+0] : lo[g*4+0]);
                float v1 = (h ? hi[g*4+1] : lo[g*4+1]);
                float v2 = (h ? hi[g*4+2] : lo[g*4+2]);
                float v3 = (h ? hi[g*4+3] : lo[g*4+3]);
                if (EPI == 1) {
                    v0 = fmaxf(v0 + bias[bn+cbase+0], 0.f);
                    v1 = fmaxf(v1 + bias[bn+cbase+1], 0.f);
                    v2 = fmaxf(v2 + bias[bn+cbase+2], 0.f);
                    v3 = fmaxf(v3 + bias[bn+cbase+3], 0.f);
                } else if (EPI == 2) {
                    const float* rr = resid + (size_t)r * ldc + bn + cbase;
                    v0 += bias[bn+cbase+0] + rr[0];
                    v1 += bias[bn+cbase+1] + rr[1];
                    v2 += bias[bn+cbase+2] + rr[2];
                    v3 += bias[bn+cbase+3] + rr[3];
                } else if (EPI == 3) {
                    const float* rr = resid + (size_t)r * ldc + bn + cbase;
                    v0 += rr[0]; v1 += rr[1]; v2 += rr[2]; v3 += rr[3];
                } else if (EPI == 4) {
                    v0 *= 0.125f; v1 *= 0.125f; v2 *= 0.125f; v3 *= 0.125f;
                    if (mask[bn+cbase+0] == 0) v0 = -1e9f;
                    if (mask[bn+cbase+1] == 0) v1 = -1e9f;
                    if (mask[bn+cbase+2] == 0) v2 = -1e9f;
                    if (mask[bn+cbase+3] == 0) v3 = -1e9f;
                }
                float4 o; o.x = v0; o.y = v1; o.z = v2; o.w = v3;
                *(float4*)(Crow + bn + cbase) = o;
            }
        }
    }
}

// ---------------------------------------------------------------------------
// Kernel wrappers
// ---------------------------------------------------------------------------
__global__ void __launch_bounds__(256, 2) k_gemm_plain(
    const float* __restrict__ A, const float* __restrict__ B, float* __restrict__ C,
    int K, int lda, int ldb, int ldc)
{
    gemm_core<128, false, 0>(A, B, C, K, lda, ldb, ldc,
                             nullptr, nullptr, nullptr,
                             blockIdx.y * 128, blockIdx.x * 128);
}
__global__ void __launch_bounds__(256, 2) k_gemm_resid(
    const float* __restrict__ A, const float* __restrict__ B, float* __restrict__ C,
    int K, int lda, int ldb, int ldc, const float* __restrict__ resid)
{
    gemm_core<128, false, 3>(A, B, C, K, lda, ldb, ldc,
                             nullptr, resid, nullptr,
                             blockIdx.y * 128, blockIdx.x * 128);
}
__global__ void __launch_bounds__(256, 2) k_gemm_bias_relu(
    const float* __restrict__ A, const float* __restrict__ B, float* __restrict__ C,
    int K, int lda, int ldb, int ldc, const float* __restrict__ bias)
{
    gemm_core<128, false, 1>(A, B, C, K, lda, ldb, ldc,
                             bias, nullptr, nullptr,
                             blockIdx.y * 128, blockIdx.x * 128);
}
__global__ void __launch_bounds__(256, 2) k_gemm_bias_resid(
    const float* __restrict__ A, const float* __restrict__ B, float* __restrict__ C,
    int K, int lda, int ldb, int ldc,
    const float* __restrict__ bias, const float* __restrict__ resid)
{
    gemm_core<128, false, 2>(A, B, C, K, lda, ldb, ldc,
                             bias, resid, nullptr,
                             blockIdx.y * 128, blockIdx.x * 128);
}
// scores[z, m, n] = (q_z[m,:] . k_z[n,:]) / 8, mask applied. z = b*16 + h.
__global__ void __launch_bounds__(256, 2) k_scores(
    const float* __restrict__ q, const float* __restrict__ k,
    const int* __restrict__ mask, float* __restrict__ sc)
{
    int z = blockIdx.z, b = z >> 4, h = z & 15;
    const float* A = q + (size_t)b * SEQ * DMODEL + h * DK;
    const float* B = k + (size_t)b * SEQ * DMODEL + h * DK;
    float* C = sc + (size_t)z * SEQ * SEQ;
    gemm_core<128, true, 4>(A, B, C, DK, DMODEL, DMODEL, SEQ,
                            nullptr, nullptr, mask + b * SEQ,
                            blockIdx.y * 128, blockIdx.x * 128);
}
// ctx[b, m, h*64+n] = sum_k attn[z,m,k] * v[b,k,h*64+n]
__global__ void __launch_bounds__(256, 2) k_ctx(
    const float* __restrict__ sc, const float* __restrict__ v,
    float* __restrict__ ctx)
{
    int z = blockIdx.z, b = z >> 4, h = z & 15;
    gemm_core<64, false, 0>(sc + (size_t)z * SEQ * SEQ,
                            v + (size_t)b * SEQ * DMODEL + h * DK,
                            ctx + (size_t)b * SEQ * DMODEL + h * DK,
                            SEQ, SEQ, DMODEL, DMODEL,
                            nullptr, nullptr, nullptr,
                            blockIdx.y * 128, 0);
}

// ---------------------------------------------------------------------------
// Launch
// ---------------------------------------------------------------------------
extern "C" void kernel_launch(void* const* d_in, const int* in_sizes, int n_in,
                              void* d_out, int out_size)
{
    const float* x      = (const float*)d_in[0];
    const int*   mask   = (const int*)  d_in[1];
    const float* wq     = (const float*)d_in[2];
    const float* wk     = (const float*)d_in[3];
    const float* wv     = (const float*)d_in[4];
    const float* wo     = (const float*)d_in[5];
    const float* w1     = (const float*)d_in[6];
    const float* b1     = (const float*)d_in[7];
    const float* w2     = (const float*)d_in[8];
    const float* b2     = (const float*)d_in[9];
    const float* alpha1 = (const float*)d_in[10];
    const float* bias1  = (const float*)d_in[11];
    const float* alpha2 = (const float*)d_in[12];
    const float* bias2  = (const float*)d_in[13];
    float* out = (float*)d_out;

    float *xn, *q, *k, *v, *ctx, *x1, *ffh, *scores;
    cudaGetSymbolAddress((void**)&xn,     g_xn);
    cudaGetSymbolAddress((void**)&q,      g_q);
    cudaGetSymbolAddress((void**)&k,      g_k);
    cudaGetSymbolAddress((void**)&v,      g_v);
    cudaGetSymbolAddress((void**)&ctx,    g_ctx);
    cudaGetSymbolAddress((void**)&x1,     g_x1);
    cudaGetSymbolAddress((void**)&ffh,    g_ffh);
    cudaGetSymbolAddress((void**)&scores, g_scores);

    // Sublayer 1: pre-norm attention
    ln_kernel<<<NTOK, 256>>>(x, xn, alpha1, bias1);

    dim3 gQKV(DMODEL / 128, NTOK / 128);            // (8, 32)
    k_gemm_plain<<<gQKV, 256>>>(xn, wq, q, DMODEL, DMODEL, DMODEL, DMODEL);
    k_gemm_plain<<<gQKV, 256>>>(xn, wk, k, DMODEL, DMODEL, DMODEL, DMODEL);
    k_gemm_plain<<<gQKV, 256>>>(xn, wv, v, DMODEL, DMODEL, DMODEL, DMODEL);

    dim3 gSc(SEQ / 128, SEQ / 128, BATCH * NHEADS); // (16, 16, 32)
    k_scores<<<gSc, 256>>>(q, k, mask, scores);

    softmax_kernel<<<BATCH * NHEADS * SEQ, 256>>>(scores);

    dim3 gCtx(1, SEQ / 128, BATCH * NHEADS);        // (1, 16, 32)
    k_ctx<<<gCtx, 256>>>(scores, v, ctx);

    // Wo projection + residual
    k_gemm_resid<<<gQKV, 256>>>(ctx, wo, x1, DMODEL, DMODEL, DMODEL, DMODEL, x);

    // Sublayer 2: pre-norm FFN
    ln_kernel<<<NTOK, 256>>>(x1, xn, alpha2, bias2);

    dim3 gF1(DFF / 128, NTOK / 128);                // (32, 32)
    k_gemm_bias_relu<<<gF1, 256>>>(xn, w1, ffh, DMODEL, DMODEL, DFF, DFF, b1);

    dim3 gF2(DMODEL / 128, NTOK / 128);             // (8, 32)
    k_gemm_bias_resid<<<gF2, 256>>>(ffh, w2, out, DFF, DFF, DMODEL, DMODEL, b2, x1);
}